// round 10
// baseline (speedup 1.0000x reference)
#include <cuda_runtime.h>
#include <cuda_bf16.h>
#include <cstdint>
#include <math.h>

#define MTOK 4096
#define SEQ  2048
#define BATCH 2
#define DIMM 2048
#define LAT  256
#define NH   16
#define HLF  64
#define HDM  128
#define LAT2 (2 * LAT)

// ---------------- scratch (device globals; no allocation allowed) ----------
__device__ __nv_bfloat16 g_pAh[MTOK * DIMM];
__device__ __nv_bfloat16 g_pAl[MTOK * DIMM];
__device__ __nv_bfloat16 g_pLh[MTOK * LAT2];
__device__ __nv_bfloat16 g_pLl[MTOK * LAT2];

__device__ __nv_bfloat16 g_Wd_h [LAT2 * DIMM],     g_Wd_l [LAT2 * DIMM];
__device__ __nv_bfloat16 g_Wqu_h[NH * HLF * LAT],  g_Wqu_l[NH * HLF * LAT];
__device__ __nv_bfloat16 g_Wku_h[NH * HLF * LAT],  g_Wku_l[NH * HLF * LAT];
__device__ __nv_bfloat16 g_Wvu_h[DIMM * LAT],      g_Wvu_l[DIMM * LAT];
__device__ __nv_bfloat16 g_Wo_h [DIMM * DIMM],     g_Wo_l [DIMM * DIMM];

__device__ __nv_bfloat16 g_qh[BATCH * NH * SEQ * HLF];
__device__ __nv_bfloat16 g_ql[BATCH * NH * SEQ * HLF];
__device__ __nv_bfloat16 g_kh[BATCH * NH * SEQ * HLF];
__device__ __nv_bfloat16 g_kl[BATCH * NH * SEQ * HLF];
__device__ __nv_bfloat16 g_vh[BATCH * NH * SEQ * HDM];
__device__ __nv_bfloat16 g_vl[BATCH * NH * SEQ * HDM];

// ---------------- helpers ---------------------------------------------------
__device__ __forceinline__ uint32_t smem_u32(const void* p) {
    uint32_t a;
    asm("{ .reg .u64 t; cvta.to.shared.u64 t, %1; cvt.u32.u64 %0, t; }" : "=r"(a) : "l"(p));
    return a;
}
__device__ __forceinline__ void cp16(uint32_t dst, const void* src) {
    asm volatile("cp.async.ca.shared.global [%0], [%1], 16;" :: "r"(dst), "l"(src) : "memory");
}
#define CP_COMMIT() asm volatile("cp.async.commit_group;" ::: "memory")
#define CP_WAIT0()  asm volatile("cp.async.wait_group 0;" ::: "memory")
#define CP_WAIT1()  asm volatile("cp.async.wait_group 1;" ::: "memory")

__device__ __forceinline__ void ldm_x4(uint32_t* r, uint32_t addr) {
    asm volatile("ldmatrix.sync.aligned.m8n8.x4.shared.b16 {%0,%1,%2,%3}, [%4];"
                 : "=r"(r[0]), "=r"(r[1]), "=r"(r[2]), "=r"(r[3]) : "r"(addr));
}
__device__ __forceinline__ void ldm_x4t(uint32_t* r, uint32_t addr) {
    asm volatile("ldmatrix.sync.aligned.m8n8.x4.trans.shared.b16 {%0,%1,%2,%3}, [%4];"
                 : "=r"(r[0]), "=r"(r[1]), "=r"(r[2]), "=r"(r[3]) : "r"(addr));
}
__device__ __forceinline__ void mma_bf16(float* d, const uint32_t* a, const uint32_t* b) {
    asm volatile("mma.sync.aligned.m16n8k16.row.col.f32.bf16.bf16.f32 "
                 "{%0,%1,%2,%3}, {%4,%5,%6,%7}, {%8,%9}, {%0,%1,%2,%3};"
                 : "+f"(d[0]), "+f"(d[1]), "+f"(d[2]), "+f"(d[3])
                 : "r"(a[0]), "r"(a[1]), "r"(a[2]), "r"(a[3]), "r"(b[0]), "r"(b[1]));
}
__device__ __forceinline__ void split2(float a, float b, uint32_t& hh, uint32_t& ll) {
    __nv_bfloat16 ha = __float2bfloat16(a), hb = __float2bfloat16(b);
    __nv_bfloat16 la = __float2bfloat16(a - __bfloat162float(ha));
    __nv_bfloat16 lb = __float2bfloat16(b - __bfloat162float(hb));
    __nv_bfloat162 hv(ha, hb), lv(la, lb);
    hh = *reinterpret_cast<uint32_t*>(&hv);
    ll = *reinterpret_cast<uint32_t*>(&lv);
}

// ---------------------------------------------------------------------------
// Fused conversion (one launch), unchanged from R9.
// ---------------------------------------------------------------------------
#define ACT_BLKS  (MTOK * DIMM / 4 / 256)
#define WT_TILES(N, K) (((N) / 32) * ((K) / 32))

__device__ __forceinline__ void wT_tile(const float* __restrict__ in,
                                        __nv_bfloat16* __restrict__ hiT,
                                        __nv_bfloat16* __restrict__ loT,
                                        int K, int N, int t, int tid, float* tbuf)
{
    int nx = N / 32;
    int n0 = (t % nx) * 32, k0 = (t / nx) * 32;
    int tx = tid & 31, ty = tid >> 5;
#pragma unroll
    for (int j = 0; j < 32; j += 8)
        tbuf[(ty + j) * 33 + tx] = in[(size_t)(k0 + ty + j) * N + n0 + tx];
    __syncthreads();
#pragma unroll
    for (int j = 0; j < 32; j += 8) {
        int n = n0 + ty + j, k = k0 + tx;
        float v = tbuf[tx * 33 + (ty + j)];
        __nv_bfloat16 h = __float2bfloat16(v);
        hiT[(size_t)n * K + k] = h;
        loT[(size_t)n * K + k] = __float2bfloat16(v - __bfloat162float(h));
    }
}

__global__ void __launch_bounds__(256) convert_all(
    const float* __restrict__ x,
    const float* __restrict__ wq_d, const float* __restrict__ wkv_d,
    const float* __restrict__ wq_u, const float* __restrict__ wk_u,
    const float* __restrict__ wv_u, const float* __restrict__ wo,
    __nv_bfloat16* __restrict__ pAh, __nv_bfloat16* __restrict__ pAl,
    __nv_bfloat16* __restrict__ Wd_h, __nv_bfloat16* __restrict__ Wd_l,
    __nv_bfloat16* __restrict__ Wqu_h, __nv_bfloat16* __restrict__ Wqu_l,
    __nv_bfloat16* __restrict__ Wku_h, __nv_bfloat16* __restrict__ Wku_l,
    __nv_bfloat16* __restrict__ Wvu_h, __nv_bfloat16* __restrict__ Wvu_l,
    __nv_bfloat16* __restrict__ Wo_h, __nv_bfloat16* __restrict__ Wo_l)
{
    __shared__ float tbuf[32 * 33];
    const int tid = threadIdx.x;
    int blk = blockIdx.x;

    if (blk < ACT_BLKS) {
        int i = blk * 256 + tid;
        float4 v = ((const float4*)x)[i];
        uint32_t h01, l01, h23, l23;
        split2(v.x, v.y, h01, l01);
        split2(v.z, v.w, h23, l23);
        ((uint32_t*)pAh)[i * 2] = h01; ((uint32_t*)pAh)[i * 2 + 1] = h23;
        ((uint32_t*)pAl)[i * 2] = l01; ((uint32_t*)pAl)[i * 2 + 1] = l23;
        return;
    }
    blk -= ACT_BLKS;

    const int T0 = WT_TILES(LAT, DIMM);
    const int T1 = T0 + WT_TILES(LAT, DIMM);
    const int T2 = T1 + WT_TILES(NH * HLF, LAT);
    const int T3 = T2 + WT_TILES(NH * HLF, LAT);
    const int T4 = T3 + WT_TILES(DIMM, LAT);

    if (blk < T0)      wT_tile(wq_d,  Wd_h,              Wd_l,              DIMM, LAT,      blk,      tid, tbuf);
    else if (blk < T1) wT_tile(wkv_d, Wd_h + LAT * DIMM, Wd_l + LAT * DIMM, DIMM, LAT,      blk - T0, tid, tbuf);
    else if (blk < T2) wT_tile(wq_u,  Wqu_h,             Wqu_l,             LAT,  NH * HLF, blk - T1, tid, tbuf);
    else if (blk < T3) wT_tile(wk_u,  Wku_h,             Wku_l,             LAT,  NH * HLF, blk - T2, tid, tbuf);
    else if (blk < T4) wT_tile(wv_u,  Wvu_h,             Wvu_l,             LAT,  DIMM,     blk - T3, tid, tbuf);
    else               wT_tile(wo,    Wo_h,              Wo_l,              DIMM, DIMM,     blk - T4, tid, tbuf);
}
#define CONV_BLKS (ACT_BLKS + 2 * WT_TILES(LAT, DIMM) + 2 * WT_TILES(NH * HLF, LAT) + \
                   WT_TILES(DIMM, LAT) + WT_TILES(DIMM, DIMM))

// ---------------------------------------------------------------------------
// mma.sync split-bf16 GEMM body; R10: 4-way interleaved mma chains.
// ---------------------------------------------------------------------------
#define KC    32
#define ROWP  40
#define PLANE (128 * ROWP * 2)
#define GBUF  (4 * PLANE)
#define GSMEM (2 * GBUF)

template<int EPI>
__device__ __forceinline__ void gemm_body(const __nv_bfloat16* __restrict__ Ah,
                                          const __nv_bfloat16* __restrict__ Al,
                                          const __nv_bfloat16* __restrict__ Bh,
                                          const __nv_bfloat16* __restrict__ Bl,
                                          void* __restrict__ O0,
                                          void* __restrict__ O1,
                                          int N, int K, int lda, float qsc,
                                          int bxt, int byt)
{
    extern __shared__ char smem[];
    const uint32_t sb = smem_u32(smem);
    const int tid = threadIdx.x, wid = tid >> 5, lane = tid & 31;
    const int m0 = byt * 128, n0 = bxt * 128;
    const int wm = wid & 3, wn = wid >> 2;

    const int row = tid >> 1, half = tid & 1;
    const __nv_bfloat16* gp[4];
    gp[0] = Ah + (size_t)(m0 + row) * lda + half * 16;
    gp[1] = Al + (size_t)(m0 + row) * lda + half * 16;
    gp[2] = Bh + (size_t)(n0 + row) * K + half * 16;
    gp[3] = Bl + (size_t)(n0 + row) * K + half * 16;
    const uint32_t sdst = (uint32_t)(row * 80 + half * 32);

    float acc[2][8][4];
#pragma unroll
    for (int mt = 0; mt < 2; mt++)
#pragma unroll
        for (int nt = 0; nt < 8; nt++)
#pragma unroll
            for (int j = 0; j < 4; j++) acc[mt][nt][j] = 0.f;

    const int lr = lane & 15;
    const int lc = (lane >> 4) << 3;
    const int bn16 = ((lane >> 4) << 3) + (lane & 7);
    const int bk = ((lane >> 3) & 1) << 3;

    const int NCH = K / KC;

#pragma unroll
    for (int p = 0; p < 4; p++) {
        cp16(sb + p * PLANE + sdst,      gp[p]);
        cp16(sb + p * PLANE + sdst + 16, gp[p] + 8);
    }
    CP_COMMIT();
    CP_WAIT0();
    __syncthreads();

    for (int i = 0; i < NCH; i++) {
        const uint32_t buf = sb + (uint32_t)((i & 1) * GBUF);

        if (i + 1 < NCH) {
            const uint32_t nbuf = sb + (uint32_t)(((i + 1) & 1) * GBUF);
            const int kof = (i + 1) * KC;
#pragma unroll
            for (int p = 0; p < 4; p++) {
                cp16(nbuf + p * PLANE + sdst,      gp[p] + kof);
                cp16(nbuf + p * PLANE + sdst + 16, gp[p] + kof + 8);
            }
            CP_COMMIT();
        }

#pragma unroll
        for (int ks = 0; ks < 2; ks++) {
            const int k0 = ks * 16;
            uint32_t ah[2][4], al[2][4];
#pragma unroll
            for (int mt = 0; mt < 2; mt++) {
                uint32_t aoff = (uint32_t)((wm * 32 + mt * 16 + lr) * 80 + (k0 + lc) * 2);
                ldm_x4(ah[mt], buf + 0 * PLANE + aoff);
                ldm_x4(al[mt], buf + 1 * PLANE + aoff);
            }
#pragma unroll
            for (int np = 0; np < 4; np++) {
                uint32_t boff = (uint32_t)((wn * 64 + np * 16 + bn16) * 80 + (k0 + bk) * 2);
                uint32_t bh4[4], bl4[4];
                ldm_x4(bh4, buf + 2 * PLANE + boff);
                ldm_x4(bl4, buf + 3 * PLANE + boff);
                const int nt0 = np * 2, nt1 = np * 2 + 1;
                // 4-way interleave; per-accumulator order preserved (bh, bl, al·bh)
                mma_bf16(acc[0][nt0], ah[0], &bh4[0]);
                mma_bf16(acc[1][nt0], ah[1], &bh4[0]);
                mma_bf16(acc[0][nt1], ah[0], &bh4[2]);
                mma_bf16(acc[1][nt1], ah[1], &bh4[2]);
                mma_bf16(acc[0][nt0], ah[0], &bl4[0]);
                mma_bf16(acc[1][nt0], ah[1], &bl4[0]);
                mma_bf16(acc[0][nt1], ah[0], &bl4[2]);
                mma_bf16(acc[1][nt1], ah[1], &bl4[2]);
                mma_bf16(acc[0][nt0], al[0], &bh4[0]);
                mma_bf16(acc[1][nt0], al[1], &bh4[0]);
                mma_bf16(acc[0][nt1], al[0], &bh4[2]);
                mma_bf16(acc[1][nt1], al[1], &bh4[2]);
            }
        }

        if (i + 1 < NCH) CP_WAIT0();
        __syncthreads();
    }

    const int er = lane >> 2, ec = (lane & 3) * 2;

    if (EPI == 0) {
        float* C = (float*)O0;
#pragma unroll
        for (int mt = 0; mt < 2; mt++) {
            float* r0 = C + (size_t)(m0 + wm * 32 + mt * 16 + er) * N + n0 + wn * 64 + ec;
            float* r1 = r0 + (size_t)8 * N;
#pragma unroll
            for (int nt = 0; nt < 8; nt++) {
                *(float2*)(r0 + nt * 8) = make_float2(acc[mt][nt][0], acc[mt][nt][1]);
                *(float2*)(r1 + nt * 8) = make_float2(acc[mt][nt][2], acc[mt][nt][3]);
            }
        }
    } else if (EPI == 1) {
        __nv_bfloat16* Hp = (__nv_bfloat16*)O0;
        __nv_bfloat16* Lp = (__nv_bfloat16*)O1;
#pragma unroll
        for (int mt = 0; mt < 2; mt++) {
            size_t r0 = (size_t)(m0 + wm * 32 + mt * 16 + er) * N + n0 + wn * 64 + ec;
            size_t r1 = r0 + (size_t)8 * N;
#pragma unroll
            for (int nt = 0; nt < 8; nt++) {
                uint32_t hh, ll;
                split2(acc[mt][nt][0], acc[mt][nt][1], hh, ll);
                *(uint32_t*)(Hp + r0 + nt * 8) = hh;
                *(uint32_t*)(Lp + r0 + nt * 8) = ll;
                split2(acc[mt][nt][2], acc[mt][nt][3], hh, ll);
                *(uint32_t*)(Hp + r1 + nt * 8) = hh;
                *(uint32_t*)(Lp + r1 + nt * 8) = ll;
            }
        }
    } else if (EPI == 2) {
        __nv_bfloat16* Hp = (__nv_bfloat16*)O0;
        __nv_bfloat16* Lp = (__nv_bfloat16*)O1;
        const int h = (n0 >> 6) + wn;
        float if0a[4], if1a[4];
#pragma unroll
        for (int t = 0; t < 4; t++) {
            int d = t * 8 + ec;
            if0a[t] = powf(10000.0f, -(float)d * (1.0f / 32.0f));
            if1a[t] = powf(10000.0f, -(float)(d + 1) * (1.0f / 32.0f));
        }
#pragma unroll
        for (int mt = 0; mt < 2; mt++) {
            int r0 = m0 + wm * 32 + mt * 16 + er;
            int s0 = r0 & (SEQ - 1), b = r0 >> 11;
            size_t base0 = (((size_t)b * NH + h) * SEQ + s0) * HLF;
            size_t base1 = base0 + (size_t)8 * HLF;
#pragma unroll
            for (int t = 0; t < 4; t++) {
                int d = t * 8 + ec;
#pragma unroll
                for (int rr = 0; rr < 2; rr++) {
                    int s = s0 + rr * 8;
                    size_t base = rr ? base1 : base0;
                    int j0 = rr * 2;
                    float sn0, cs0, sn1, cs1;
                    sincosf((float)s * if0a[t], &sn0, &cs0);
                    sincosf((float)s * if1a[t], &sn1, &cs1);
                    float lo0 = acc[mt][t][j0],     lo1 = acc[mt][t][j0 + 1];
                    float hi0 = acc[mt][t + 4][j0], hi1 = acc[mt][t + 4][j0 + 1];
                    float nl0 = (lo0 * cs0 - hi0 * sn0) * qsc;
                    float nh0 = (hi0 * cs0 + lo0 * sn0) * qsc;
                    float nl1 = (lo1 * cs1 - hi1 * sn1) * qsc;
                    float nh1 = (hi1 * cs1 + lo1 * sn1) * qsc;
                    uint32_t H, L;
                    split2(nl0, nl1, H, L);
                    *(uint32_t*)(Hp + base + d) = H;
                    *(uint32_t*)(Lp + base + d) = L;
                    split2(nh0, nh1, H, L);
                    *(uint32_t*)(Hp + base + d + 32) = H;
                    *(uint32_t*)(Lp + base + d + 32) = L;
                }
            }
        }
    } else {  // EPI == 4
        __nv_bfloat16* Hp = (__nv_bfloat16*)O0;
        __nv_bfloat16* Lp = (__nv_bfloat16*)O1;
        const int col64 = n0 + wn * 64;
        const int h = col64 >> 7;
        const int db = (col64 & 64) + ec;
#pragma unroll
        for (int mt = 0; mt < 2; mt++) {
            int r0 = m0 + wm * 32 + mt * 16 + er;
            int s0 = r0 & (SEQ - 1), b = r0 >> 11;
            size_t base0 = (((size_t)b * NH + h) * SEQ + s0) * HDM;
            size_t base1 = base0 + (size_t)8 * HDM;
#pragma unroll
            for (int nt = 0; nt < 8; nt++) {
                int d = db + nt * 8;
                uint32_t H, L;
                split2(acc[mt][nt][0], acc[mt][nt][1], H, L);
                *(uint32_t*)(Hp + base0 + d) = H;
                *(uint32_t*)(Lp + base0 + d) = L;
                split2(acc[mt][nt][2], acc[mt][nt][3], H, L);
                *(uint32_t*)(Hp + base1 + d) = H;
                *(uint32_t*)(Lp + base1 + d) = L;
            }
        }
    }
}

template<int EPI>
__global__ void __launch_bounds__(256, 2) gemm_g(const __nv_bfloat16* __restrict__ Ah,
                                                 const __nv_bfloat16* __restrict__ Al,
                                                 const __nv_bfloat16* __restrict__ Bh,
                                                 const __nv_bfloat16* __restrict__ Bl,
                                                 void* __restrict__ O0,
                                                 void* __restrict__ O1,
                                                 int N, int K, int lda)
{
    gemm_body<EPI>(Ah, Al, Bh, Bl, O0, O1, N, K, lda, 1.0f, blockIdx.x, blockIdx.y);
}

__global__ void __launch_bounds__(256, 2) gemm_qkv(
    const __nv_bfloat16* __restrict__ pLh, const __nv_bfloat16* __restrict__ pLl,
    const __nv_bfloat16* __restrict__ Bqh, const __nv_bfloat16* __restrict__ Bql,
    const __nv_bfloat16* __restrict__ Bkh, const __nv_bfloat16* __restrict__ Bkl,
    const __nv_bfloat16* __restrict__ Bvh, const __nv_bfloat16* __restrict__ Bvl,
    __nv_bfloat16* __restrict__ qh, __nv_bfloat16* __restrict__ ql,
    __nv_bfloat16* __restrict__ kh, __nv_bfloat16* __restrict__ kl,
    __nv_bfloat16* __restrict__ vh, __nv_bfloat16* __restrict__ vl)
{
    const int bx = blockIdx.x, by = blockIdx.y;
    if (bx < 8)
        gemm_body<2>(pLh, pLl, Bqh, Bql, qh, ql, NH * HLF, LAT, LAT2, 0.125f, bx, by);
    else if (bx < 16)
        gemm_body<2>(pLh + LAT, pLl + LAT, Bkh, Bkl, kh, kl, NH * HLF, LAT, LAT2, 1.0f, bx - 8, by);
    else
        gemm_body<4>(pLh + LAT, pLl + LAT, Bvh, Bvl, vh, vl, DIMM, LAT, LAT2, 1.0f, bx - 16, by);
}

// ---------------------------------------------------------------------------
// Flash attention; R10: interleaved mma chains in QK and PV.
// ---------------------------------------------------------------------------
#define ACHUNK 64
#define NCH_A  (SEQ / ACHUNK)
#define QPITCH 144
#define KPITCH 144
#define VPITCH 272
#define SQH 0
#define SQL 18432
#define SK0 36864
#define KBUF 18432
#define SV0 73728
#define VBUF 34816
#define ASMEM 143360

__device__ __forceinline__ void load_kv_chunk(uint32_t kdst, uint32_t vdst,
    const __nv_bfloat16* kh, const __nv_bfloat16* kl,
    const __nv_bfloat16* vh, const __nv_bfloat16* vl, int tid)
{
    int row = tid >> 2;
    int ksg = (tid & 3) * 2;
#pragma unroll
    for (int j = 0; j < 2; j++) {
        cp16(kdst +        row * KPITCH + (ksg + j) * 16, kh + row * HLF + (ksg + j) * 8);
        cp16(kdst + 9216 + row * KPITCH + (ksg + j) * 16, kl + row * HLF + (ksg + j) * 8);
    }
    int vsg = (tid & 3) * 4;
#pragma unroll
    for (int j = 0; j < 4; j++) {
        cp16(vdst +         row * VPITCH + (vsg + j) * 16, vh + row * HDM + (vsg + j) * 8);
        cp16(vdst + 17408 + row * VPITCH + (vsg + j) * 16, vl + row * HDM + (vsg + j) * 8);
    }
}

__global__ void __launch_bounds__(256, 1) attn_mma(
    const __nv_bfloat16* __restrict__ Qh, const __nv_bfloat16* __restrict__ Ql,
    const __nv_bfloat16* __restrict__ Kh, const __nv_bfloat16* __restrict__ Kl,
    const __nv_bfloat16* __restrict__ Vh, const __nv_bfloat16* __restrict__ Vl,
    __nv_bfloat16* __restrict__ Oh, __nv_bfloat16* __restrict__ Ol)
{
    extern __shared__ char smem[];
    const uint32_t sb = smem_u32(smem);
    const int tid = threadIdx.x, wid = tid >> 5, lane = tid & 31;
    const int q0 = blockIdx.x * 128;
    const int h = blockIdx.y, b = blockIdx.z;
    const size_t bh = (size_t)b * NH + h;

    const __nv_bfloat16* qhg = Qh + (bh * SEQ + q0) * HLF;
    const __nv_bfloat16* qlg = Ql + (bh * SEQ + q0) * HLF;
    const __nv_bfloat16* khg = Kh + bh * SEQ * HLF;
    const __nv_bfloat16* klg = Kl + bh * SEQ * HLF;
    const __nv_bfloat16* vhg = Vh + bh * SEQ * HDM;
    const __nv_bfloat16* vlg = Vl + bh * SEQ * HDM;

    {
        int row = tid >> 1, sg = (tid & 1) * 4;
#pragma unroll
        for (int j = 0; j < 4; j++) {
            cp16(sb + SQH + row * QPITCH + (sg + j) * 16, qhg + row * HLF + (sg + j) * 8);
            cp16(sb + SQL + row * QPITCH + (sg + j) * 16, qlg + row * HLF + (sg + j) * 8);
        }
    }
    load_kv_chunk(sb + SK0, sb + SV0, khg, klg, vhg, vlg, tid);
    CP_COMMIT();
    CP_WAIT0();
    __syncthreads();

    uint32_t qfh[4][4], qfl[4][4];
    {
        int lr = lane & 15, lc = (lane >> 4) << 3;
#pragma unroll
        for (int ks = 0; ks < 4; ks++) {
            uint32_t aoff = (uint32_t)((wid * 16 + lr) * QPITCH + (ks * 16 + lc) * 2);
            ldm_x4(qfh[ks], sb + SQH + aoff);
            ldm_x4(qfl[ks], sb + SQL + aoff);
        }
    }

    float ao[16][4];
#pragma unroll
    for (int nt = 0; nt < 16; nt++)
#pragma unroll
        for (int j = 0; j < 4; j++) ao[nt][j] = 0.f;
    float m0 = -1e30f, m1 = -1e30f, l0 = 0.f, l1 = 0.f;

    const int brow = lane & 7;
    const int bcol8 = (lane >> 3) * 8;
    const int vrow = (lane & 7) + ((lane >> 3) & 1) * 8;
    const int vcol = (lane >> 4) * 8;

    for (int kt = 0; kt < NCH_A; kt++) {
        const uint32_t kb = sb + SK0 + (uint32_t)((kt & 1) * KBUF);
        const uint32_t vb = sb + SV0 + (uint32_t)((kt & 1) * VBUF);

        if (kt + 1 < NCH_A) {
            load_kv_chunk(sb + SK0 + (uint32_t)(((kt + 1) & 1) * KBUF),
                          sb + SV0 + (uint32_t)(((kt + 1) & 1) * VBUF),
                          khg + (size_t)(kt + 1) * ACHUNK * HLF,
                          klg + (size_t)(kt + 1) * ACHUNK * HLF,
                          vhg + (size_t)(kt + 1) * ACHUNK * HDM,
                          vlg + (size_t)(kt + 1) * ACHUNK * HDM, tid);
            CP_COMMIT();
            CP_WAIT1();
        } else {
            CP_WAIT0();
        }
        __syncthreads();

        float sc[8][4];
#pragma unroll
        for (int nt = 0; nt < 8; nt++)
#pragma unroll
            for (int j = 0; j < 4; j++) sc[nt][j] = 0.f;

        // ---- S = Q K^T : two independent accumulator chains interleaved ----
#pragma unroll
        for (int ntq = 0; ntq < 4; ntq++) {
            const int n0t = ntq * 2, n1t = ntq * 2 + 1;
#pragma unroll
            for (int kp = 0; kp < 2; kp++) {
                uint32_t off0 = (uint32_t)((n0t * 8 + brow) * KPITCH + (kp * 32 + bcol8) * 2);
                uint32_t off1 = (uint32_t)((n1t * 8 + brow) * KPITCH + (kp * 32 + bcol8) * 2);
                uint32_t kfh0[4], kfl0[4], kfh1[4], kfl1[4];
                ldm_x4(kfh0, kb + off0);
                ldm_x4(kfl0, kb + 9216 + off0);
                ldm_x4(kfh1, kb + off1);
                ldm_x4(kfl1, kb + 9216 + off1);
                // per-acc order preserved: h·h, h·l, l·h (k-lo then k-hi halves)
                mma_bf16(sc[n0t], qfh[2 * kp],     &kfh0[0]);
                mma_bf16(sc[n1t], qfh[2 * kp],     &kfh1[0]);
                mma_bf16(sc[n0t], qfh[2 * kp],     &kfl0[0]);
                mma_bf16(sc[n1t], qfh[2 * kp],     &kfl1[0]);
                mma_bf16(sc[n0t], qfl[2 * kp],     &kfh0[0]);
                mma_bf16(sc[n1t], qfl[2 * kp],     &kfh1[0]);
                mma_bf16(sc[n0t], qfh[2 * kp + 1], &kfh0[2]);
                mma_bf16(sc[n1t], qfh[2 * kp + 1], &kfh1[2]);
                mma_bf16(sc[n0t], qfh[2 * kp + 1], &kfl0[2]);
                mma_bf16(sc[n1t], qfh[2 * kp + 1], &kfl1[2]);
                mma_bf16(sc[n0t], qfl[2 * kp + 1], &kfh0[2]);
                mma_bf16(sc[n1t], qfl[2 * kp + 1], &kfh1[2]);
            }
        }

        float mx0 = -1e30f, mx1 = -1e30f;
#pragma unroll
        for (int nt = 0; nt < 8; nt++) {
            mx0 = fmaxf(mx0, fmaxf(sc[nt][0], sc[nt][1]));
            mx1 = fmaxf(mx1, fmaxf(sc[nt][2], sc[nt][3]));
        }
        mx0 = fmaxf(mx0, __shfl_xor_sync(0xffffffffu, mx0, 1));
        mx0 = fmaxf(mx0, __shfl_xor_sync(0xffffffffu, mx0, 2));
        mx1 = fmaxf(mx1, __shfl_xor_sync(0xffffffffu, mx1, 1));
        mx1 = fmaxf(mx1, __shfl_xor_sync(0xffffffffu, mx1, 2));
        float mn0 = fmaxf(m0, mx0), mn1 = fmaxf(m1, mx1);
        float al0 = __expf(m0 - mn0), al1 = __expf(m1 - mn1);
        m0 = mn0; m1 = mn1;
        float s0 = 0.f, s1 = 0.f;
#pragma unroll
        for (int nt = 0; nt < 8; nt++) {
            sc[nt][0] = __expf(sc[nt][0] - mn0); s0 += sc[nt][0];
            sc[nt][1] = __expf(sc[nt][1] - mn0); s0 += sc[nt][1];
            sc[nt][2] = __expf(sc[nt][2] - mn1); s1 += sc[nt][2];
            sc[nt][3] = __expf(sc[nt][3] - mn1); s1 += sc[nt][3];
        }
        s0 += __shfl_xor_sync(0xffffffffu, s0, 1);
        s0 += __shfl_xor_sync(0xffffffffu, s0, 2);
        s1 += __shfl_xor_sync(0xffffffffu, s1, 1);
        s1 += __shfl_xor_sync(0xffffffffu, s1, 2);
        l0 = l0 * al0 + s0;
        l1 = l1 * al1 + s1;
#pragma unroll
        for (int nt = 0; nt < 16; nt++) {
            ao[nt][0] *= al0; ao[nt][1] *= al0;
            ao[nt][2] *= al1; ao[nt][3] *= al1;
        }

        uint32_t ph[4][4], pl[4][4];
#pragma unroll
        for (int t = 0; t < 4; t++) {
            split2(sc[2 * t][0],     sc[2 * t][1],     ph[t][0], pl[t][0]);
            split2(sc[2 * t][2],     sc[2 * t][3],     ph[t][1], pl[t][1]);
            split2(sc[2 * t + 1][0], sc[2 * t + 1][1], ph[t][2], pl[t][2]);
            split2(sc[2 * t + 1][2], sc[2 * t + 1][3], ph[t][3], pl[t][3]);
        }

        // ---- O += P V : two accumulator chains interleaved ----
#pragma unroll
        for (int ntp = 0; ntp < 8; ntp++) {
#pragma unroll
            for (int t = 0; t < 4; t++) {
                uint32_t off = (uint32_t)((t * 16 + vrow) * VPITCH + (ntp * 16 + vcol) * 2);
                uint32_t vfh[4], vfl[4];
                ldm_x4t(vfh, vb + off);
                ldm_x4t(vfl, vb + 17408 + off);
                // per-acc order preserved: ph·vh, ph·vl, pl·vh
                mma_bf16(ao[2 * ntp],     ph[t], &vfh[0]);
                mma_bf16(ao[2 * ntp + 1], ph[t], &vfh[2]);
                mma_bf16(ao[2 * ntp],     ph[t], &vfl[0]);
                mma_bf16(ao[2 * ntp + 1], ph[t], &vfl[2]);
                mma_bf16(ao[2 * ntp],     pl[t], &vfh[0]);
                mma_bf16(ao[2 * ntp + 1], pl[t], &vfh[2]);
            }
        }
        __syncthreads();
    }

    const int g = lane >> 2, c2 = (lane & 3) * 2;
    float i0 = 1.0f / l0, i1 = 1.0f / l1;
    size_t tok0 = (size_t)b * SEQ + q0 + wid * 16 + g;
    __nv_bfloat16* oh0 = Oh + tok0 * DIMM + h * HDM + c2;
    __nv_bfloat16* ol0 = Ol + tok0 * DIMM + h * HDM + c2;
    __nv_bfloat16* oh1 = oh0 + (size_t)8 * DIMM;
    __nv_bfloat16* ol1 = ol0 + (size_t)8 * DIMM;
#pragma unroll
    for (int nt = 0; nt < 16; nt++) {
        uint32_t hh, ll;
        split2(ao[nt][0] * i0, ao[nt][1] * i0, hh, ll);
        *(uint32_t*)(oh0 + nt * 8) = hh;
        *(uint32_t*)(ol0 + nt * 8) = ll;
        split2(ao[nt][2] * i1, ao[nt][3] * i1, hh, ll);
        *(uint32_t*)(oh1 + nt * 8) = hh;
        *(uint32_t*)(ol1 + nt * 8) = ll;
    }
}

// ---------------------------------------------------------------------------
extern "C" void kernel_launch(void* const* d_in, const int* in_sizes, int n_in,
                              void* d_out, int out_size)
{
    const float* x     = (const float*)d_in[0];
    const float* wq_d  = (const float*)d_in[1];
    const float* wkv_d = (const float*)d_in[2];
    const float* wq_u  = (const float*)d_in[3];
    const float* wk_u  = (const float*)d_in[4];
    const float* wv_u  = (const float*)d_in[5];
    const float* wo    = (const float*)d_in[6];
    float* out = (float*)d_out;

    __nv_bfloat16 *pAh, *pAl, *pLh, *pLl;
    __nv_bfloat16 *Wd_h, *Wd_l, *Wqu_h, *Wqu_l, *Wku_h, *Wku_l, *Wvu_h, *Wvu_l, *Wo_h, *Wo_l;
    __nv_bfloat16 *qh, *ql, *kh, *kl, *vh, *vl;
    cudaGetSymbolAddress((void**)&pAh,   g_pAh);
    cudaGetSymbolAddress((void**)&pAl,   g_pAl);
    cudaGetSymbolAddress((void**)&pLh,   g_pLh);
    cudaGetSymbolAddress((void**)&pLl,   g_pLl);
    cudaGetSymbolAddress((void**)&Wd_h,  g_Wd_h);   cudaGetSymbolAddress((void**)&Wd_l,  g_Wd_l);
    cudaGetSymbolAddress((void**)&Wqu_h, g_Wqu_h);  cudaGetSymbolAddress((void**)&Wqu_l, g_Wqu_l);
    cudaGetSymbolAddress((void**)&Wku_h, g_Wku_h);  cudaGetSymbolAddress((void**)&Wku_l, g_Wku_l);
    cudaGetSymbolAddress((void**)&Wvu_h, g_Wvu_h);  cudaGetSymbolAddress((void**)&Wvu_l, g_Wvu_l);
    cudaGetSymbolAddress((void**)&Wo_h,  g_Wo_h);   cudaGetSymbolAddress((void**)&Wo_l,  g_Wo_l);
    cudaGetSymbolAddress((void**)&qh,    g_qh);
    cudaGetSymbolAddress((void**)&ql,    g_ql);
    cudaGetSymbolAddress((void**)&kh,    g_kh);
    cudaGetSymbolAddress((void**)&kl,    g_kl);
    cudaGetSymbolAddress((void**)&vh,    g_vh);
    cudaGetSymbolAddress((void**)&vl,    g_vl);

    cudaFuncSetAttribute(gemm_g<0>, cudaFuncAttributeMaxDynamicSharedMemorySize, GSMEM);
    cudaFuncSetAttribute(gemm_g<1>, cudaFuncAttributeMaxDynamicSharedMemorySize, GSMEM);
    cudaFuncSetAttribute(gemm_qkv,  cudaFuncAttributeMaxDynamicSharedMemorySize, GSMEM);
    cudaFuncSetAttribute(attn_mma,  cudaFuncAttributeMaxDynamicSharedMemorySize, ASMEM);

    convert_all<<<CONV_BLKS, 256>>>(x, wq_d, wkv_d, wq_u, wk_u, wv_u, wo,
                                    pAh, pAl, Wd_h, Wd_l, Wqu_h, Wqu_l,
                                    Wku_h, Wku_l, Wvu_h, Wvu_l, Wo_h, Wo_l);

    gemm_g<1><<<dim3(LAT2 / 128, MTOK / 128), 256, GSMEM>>>(
        pAh, pAl, Wd_h, Wd_l, pLh, pLl, LAT2, DIMM, DIMM);

    gemm_qkv<<<dim3(32, MTOK / 128), 256, GSMEM>>>(
        pLh, pLl, Wqu_h, Wqu_l, Wku_h, Wku_l, Wvu_h, Wvu_l,
        qh, ql, kh, kl, vh, vl);

    attn_mma<<<dim3(SEQ / 128, NH, BATCH), 256, ASMEM>>>(qh, ql, kh, kl, vh, vl, pAh, pAl);

    gemm_g<0><<<dim3(DIMM / 128, MTOK / 128), 256, GSMEM>>>(
        pAh, pAl, Wo_h, Wo_l, out, nullptr, DIMM, DIMM, DIMM);
}